// round 11
// baseline (speedup 1.0000x reference)
#include <cuda_runtime.h>
#include <math.h>

#define BB 2
#define CC 128
#define HH 48
#define WW 48
#define PP (HH*WW)      // 2304
#define BPP (BB*PP)     // 4608
#define HD 24
#define WIN 13
#define KK2 169
#define NG 32
#define NT 72

typedef unsigned long long ull;

// ---------------- scratch (static device globals; no allocation) ----------------
__device__ float g_xt[BB*PP*CC];         // x transposed, pixel-major [b,p,c]
__device__ float g_xn[BB*PP*CC];         // normalized x, pixel-major [pix][c]
__device__ float g_m[BPP];
__device__ float g_df[BPP];
__device__ int   g_dmin[BB];
__device__ int   g_dmax[BB];
__device__ float g_gps[BB*NG*NT];
__device__ float g_gpq[BB*NG*NT];
__device__ float g_mu[BB*NG];
__device__ float g_rstd[BB*NG];
__device__ float g_enh[BB*PP*CC];

__device__ __forceinline__ void fma2(ull& d, ull a, ull b, ull c) {
    asm("fma.rn.f32x2 %0, %1, %2, %3;" : "=l"(d) : "l"(a), "l"(b), "l"(c));
}
__device__ __forceinline__ void add2(ull& d, ull a, ull b) {
    asm("add.rn.f32x2 %0, %1, %2;" : "=l"(d) : "l"(a), "l"(b));
}
__device__ __forceinline__ ull dup2(float v) {
    ull r; unsigned u = __float_as_uint(v);
    asm("mov.b64 %0, {%1, %1};" : "=l"(r) : "r"(u));
    return r;
}
__device__ __forceinline__ ull pack2(float a, float b) {
    ull r; asm("mov.b64 %0, {%1, %2};" : "=l"(r) : "r"(__float_as_uint(a)), "r"(__float_as_uint(b)));
    return r;
}
__device__ __forceinline__ float lo2(ull v) { return __uint_as_float((unsigned)(v & 0xffffffffull)); }
__device__ __forceinline__ float hi2(ull v) { return __uint_as_float((unsigned)(v >> 32)); }
__device__ __forceinline__ int refl(int v, int n) {
    return v < 0 ? -v : (v >= n ? 2 * n - 2 - v : v);
}
// jax bilinear 24->48 weights (edge-renormalized triangle)
__device__ __forceinline__ void upw(int o, int& i0, float& w0, int& i1, float& w1v) {
    if (o & 1) { i0 = (o - 1) >> 1; i1 = i0 + 1; w0 = 0.75f; w1v = 0.25f;
                 if (i1 >= HD) { i1 = i0; w0 = 1.0f; w1v = 0.0f; } }
    else       { i1 = o >> 1; i0 = i1 - 1; w1v = 0.75f; w0 = 0.25f;
                 if (i0 < 0) { i0 = i1; w0 = 0.0f; w1v = 1.0f; } }
}

// ---------------- k_t: NCHW -> pixel-major transpose + GN partial sums + init ----------------
__global__ void __launch_bounds__(256) k_t(const float* __restrict__ x) {
    __shared__ float tile[32][33];
    __shared__ float sS[8][4], sQ[8][4];
    int tx = threadIdx.x & 31, ty = threadIdx.x >> 5;
    int tb = blockIdx.x, cb = blockIdx.y, b = blockIdx.z;
    if (tb == 0 && cb == 0 && b == 0 && threadIdx.x < BB) {
        g_dmin[threadIdx.x] = 0x7f7fffff; g_dmax[threadIdx.x] = 0;
    }
    int c0 = cb * 32, p0 = tb * 32;
    #pragma unroll
    for (int k = 0; k < 4; k++) {
        int c = c0 + ty + 8 * k;
        float v = x[(b * CC + c) * PP + p0 + tx];
        tile[ty + 8 * k][tx] = v;
        float s = v, q = v * v;
        #pragma unroll
        for (int off = 16; off; off >>= 1) {
            s += __shfl_xor_sync(~0u, s, off);
            q += __shfl_xor_sync(~0u, q, off);
        }
        if (tx == 0) { sS[ty][k] = s; sQ[ty][k] = q; }
    }
    __syncthreads();
    #pragma unroll
    for (int k = 0; k < 4; k++) {
        int p = p0 + ty + 8 * k;
        g_xt[(b * PP + p) * CC + c0 + tx] = tile[tx][ty + 8 * k];
    }
    if (threadIdx.x < 8) {
        int k = threadIdx.x >> 1, m = threadIdx.x & 1;
        float s = sS[4*m][k] + sS[4*m+1][k] + sS[4*m+2][k] + sS[4*m+3][k];
        float q = sQ[4*m][k] + sQ[4*m+1][k] + sQ[4*m+2][k] + sQ[4*m+3][k];
        int g = 8 * cb + threadIdx.x;
        g_gps[(b * NG + g) * NT + tb] = s;
        g_gpq[(b * NG + g) * NT + tb] = q;
    }
}

// ---------------- k_pix: warp/pixel; inline 2x2-mean taps, df, norm, GN finalize ----------------
__global__ void __launch_bounds__(256) k_pix() {
    if (blockIdx.x < BB * NG) {                   // GN finalize (g_gps from k_t)
        __shared__ float fs[NT], fq[NT];
        int bg = blockIdx.x;
        if (threadIdx.x < NT) {
            fs[threadIdx.x] = g_gps[bg * NT + threadIdx.x];
            fq[threadIdx.x] = g_gpq[bg * NT + threadIdx.x];
        }
        __syncthreads();
        if (threadIdx.x == 0) {
            float s = 0.f, q = 0.f;
            for (int i = 0; i < NT; i++) { s += fs[i]; q += fq[i]; }
            const float invn = 1.0f / (4.0f * PP);
            float mu = s * invn;
            float var = q * invn - mu * mu;
            g_mu[bg] = mu;
            g_rstd[bg] = rsqrtf(var + 1e-5f);
        }
    }

    int warp = threadIdx.x >> 5, lane = threadIdx.x & 31;
    int pix = blockIdx.x * 8 + warp;              // 576*8 = 4608
    int b = pix / PP, p = pix - b * PP;
    int h = p / WW, w = p - h * WW;
    const float4 v4 = *(const float4*)(g_xt + pix * CC + 4 * lane);

    int r0, r1, c0, c1; float wr0, wr1, wc0, wc1;
    upw(h, r0, wr0, r1, wr1);
    upw(w, c0, wc0, c1, wc1);

    const float* xb = g_xt + b * PP * CC + 4 * lane;
    float4 dv[2][2];
    #pragma unroll
    for (int rr = 0; rr < 2; rr++) {
        int r = rr ? r1 : r0;
        #pragma unroll
        for (int cc2 = 0; cc2 < 2; cc2++) {
            int c = cc2 ? c1 : c0;
            const float* bp = xb + ((2 * r) * WW + 2 * c) * CC;
            float4 a0 = *(const float4*)(bp);
            float4 a1 = *(const float4*)(bp + CC);
            float4 a2 = *(const float4*)(bp + WW * CC);
            float4 a3 = *(const float4*)(bp + WW * CC + CC);
            dv[rr][cc2].x = 0.25f * (a0.x + a1.x + a2.x + a3.x);
            dv[rr][cc2].y = 0.25f * (a0.y + a1.y + a2.y + a3.y);
            dv[rr][cc2].z = 0.25f * (a0.z + a1.z + a2.z + a3.z);
            dv[rr][cc2].w = 0.25f * (a0.w + a1.w + a2.w + a3.w);
        }
    }
    float x0 = wr0 * (wc0 * dv[0][0].x + wc1 * dv[0][1].x) + wr1 * (wc0 * dv[1][0].x + wc1 * dv[1][1].x);
    float x1 = wr0 * (wc0 * dv[0][0].y + wc1 * dv[0][1].y) + wr1 * (wc0 * dv[1][0].y + wc1 * dv[1][1].y);
    float x2 = wr0 * (wc0 * dv[0][0].z + wc1 * dv[0][1].z) + wr1 * (wc0 * dv[1][0].z + wc1 * dv[1][1].z);
    float x3 = wr0 * (wc0 * dv[0][0].w + wc1 * dv[0][1].w) + wr1 * (wc0 * dv[1][0].w + wc1 * dv[1][1].w);

    float a = fabsf(v4.x - x0) + fabsf(v4.y - x1) + fabsf(v4.z - x2) + fabsf(v4.w - x3);
    float q = v4.x * v4.x + v4.y * v4.y + v4.z * v4.z + v4.w * v4.w;
    #pragma unroll
    for (int off = 16; off; off >>= 1) {
        a += __shfl_xor_sync(~0u, a, off);
        q += __shfl_xor_sync(~0u, q, off);
    }
    float m = fmaxf(sqrtf(q), 1e-12f);
    if (lane == 0) {
        g_df[pix] = a;
        atomicMin(&g_dmin[b], __float_as_int(a));
        atomicMax(&g_dmax[b], __float_as_int(a));
        g_m[pix] = m;
    }
    float inv = 1.0f / m;
    float4 o; o.x = v4.x * inv; o.y = v4.y * inv; o.z = v4.z * inv; o.w = v4.w * inv;
    *(float4*)(g_xn + pix * CC + 4 * lane) = o;
}

// ---------------- k_main: sims (multi-value butterfly, measured 34us) + stable top-k + gather + GN ----------------
__global__ void __launch_bounds__(256) k_main(const float* __restrict__ gamma,
                                              const float* __restrict__ beta) {
    int warp = threadIdx.x >> 5, lane = threadIdx.x & 31;
    int pix = blockIdx.x * 8 + warp;
    int b = pix / PP, p = pix - b * PP;
    int h = p / WW, w = p - h * WW;
    const float* xnb = g_xn + b * PP * CC;
    const float4 xp4 = *(const float4*)(xnb + p * CC + 4 * lane);

    float df = g_df[pix];
    float dmin = __int_as_float(g_dmin[b]);
    float dmax = __int_as_float(g_dmax[b]);
    float dn = (df - dmin) / (dmax - dmin + 1e-8f);
    int kcnt = (int)(1.0f + rintf(dn * 15.0f));
    if (kcnt < 1) kcnt = 1;
    if (kcnt > 16) kcnt = 16;

    int rbase[WIN], qo[WIN];
    #pragma unroll
    for (int t = 0; t < WIN; t++) {
        rbase[t] = refl(h + t - 6, HH) * WW * CC;
        qo[t]    = refl(w + t - 6, WW) * CC;
    }

    float sreg[6];
    #pragma unroll
    for (int r = 0; r < 6; r++) {
        float v[32];
        #pragma unroll
        for (int jj = 0; jj < 32; jj++) {
            const int kk = r * 32 + jj;
            const int ii = (kk < KK2) ? kk / WIN : 0;
            const int ij = (kk < KK2) ? kk - ii * WIN : 0;
            const float4 vq = *(const float4*)(xnb + rbase[ii] + qo[ij] + 4 * lane);
            v[jj] = xp4.x * vq.x + xp4.y * vq.y + xp4.z * vq.z + xp4.w * vq.w;
        }
        #pragma unroll
        for (int off = 16; off >= 1; off >>= 1) {
            bool up = (lane & off) != 0;
            #pragma unroll
            for (int j = 0; j < off; j++) {
                float send = up ? v[j] : v[j + off];
                float recv = __shfl_xor_sync(~0u, send, off);
                v[j] = (up ? v[j + off] : v[j]) + recv;
            }
        }
        sreg[r] = v[0];
    }
    if (160 + lane >= KK2) sreg[5] = -1e30f;

    unsigned taken = 0;
    int selk[16]; float selw[16];
    float sumexp = 0.f;
    #pragma unroll
    for (int it = 0; it < 16; it++) {
        if (it < kcnt) {
            float bv = -1e30f; int bt = 0;
            #pragma unroll
            for (int t = 0; t < 6; t++) {
                float cand = (taken & (1u << t)) ? -1e30f : sreg[t];
                if (cand > bv) { bv = cand; bt = t; }
            }
            int bk = lane + 32 * bt;
            #pragma unroll
            for (int off = 16; off; off >>= 1) {
                float ov = __shfl_xor_sync(~0u, bv, off);
                int   ok = __shfl_xor_sync(~0u, bk, off);
                if (ov > bv || (ov == bv && ok < bk)) { bv = ov; bk = ok; }
            }
            if (lane == (bk & 31)) taken |= (1u << (bk >> 5));
            float e = __expf(bv);
            selk[it] = bk; selw[it] = e; sumexp += e;
        }
    }

    float inv = 1.0f / sumexp;
    float4 out4 = make_float4(0.f, 0.f, 0.f, 0.f);
    #pragma unroll
    for (int it = 0; it < 16; it++) {
        if (it < kcnt) {
            int kk = selk[it];
            int ii = kk / WIN, jj = kk - ii * WIN;
            int r = refl(h + ii - 6, HH);
            int cq = refl(w + jj - 6, WW);
            int q = r * WW + cq;
            float wgt = selw[it] * inv * g_m[b * PP + q];
            const float4 vq = *(const float4*)(xnb + q * CC + 4 * lane);
            out4.x += wgt * vq.x; out4.y += wgt * vq.y;
            out4.z += wgt * vq.z; out4.w += wgt * vq.w;
        }
    }

    float mp = g_m[pix];
    float mu = g_mu[b * NG + lane];
    float rs = g_rstd[b * NG + lane];
    float4 gm  = *(const float4*)(gamma + 4 * lane);
    float4 bt4 = *(const float4*)(beta + 4 * lane);
    float4 e4;
    e4.x = out4.x + (xp4.x * mp - mu) * rs * gm.x + bt4.x;
    e4.y = out4.y + (xp4.y * mp - mu) * rs * gm.y + bt4.y;
    e4.z = out4.z + (xp4.z * mp - mu) * rs * gm.z + bt4.z;
    e4.w = out4.w + (xp4.w * mp - mu) * rs * gm.w + bt4.w;
    *(float4*)(g_enh + pix * CC + 4 * lane) = e4;
}

// ---------------- k_ffn: GEMM pair, 8:1 FMA2:LDS tiles, f32x2, 48KB smem ----------------
__global__ void __launch_bounds__(256) k_ffn(const float* __restrict__ w1,
                                             const float* __restrict__ b1,
                                             const float* __restrict__ w2,
                                             const float* __restrict__ b2,
                                             float* __restrict__ out) {
    __shared__ __align__(16) ull sE_u[128 * 16];   // [k][px-pair], 16KB
    __shared__ __align__(16) ull sH_u[256 * 16];   // [n][px-pair], 32KB
    float* sE_f = (float*)sE_u;
    int tid = threadIdx.x;
    int pix0 = blockIdx.x * 32;
    int b = pix0 / PP;

    {
        const float4* eg = (const float4*)(g_enh + pix0 * CC);
        #pragma unroll
        for (int i = 0; i < 4; i++) {
            int idx = tid + 256 * i;
            int p = idx >> 5, c4 = idx & 31;
            float4 v = eg[idx];
            sE_f[(4 * c4 + 0) * 32 + p] = v.x;
            sE_f[(4 * c4 + 1) * 32 + p] = v.y;
            sE_f[(4 * c4 + 2) * 32 + p] = v.z;
            sE_f[(4 * c4 + 3) * 32 + p] = v.w;
        }
    }
    __syncthreads();

    {   // GEMM1: thread = 4n x 8px; per kt: 8 LDS.128 + 64 FMA2 (8:1)
        int pi = tid & 3;          // px group: 8 px (4 ull)
        int ni = tid >> 2;         // 0..63 -> n = ni*4..+3
        ull acc[4][4];
        #pragma unroll
        for (int m = 0; m < 4; m++)
            #pragma unroll
            for (int j = 0; j < 4; j++) acc[m][j] = 0ull;
        const float4* w1v4 = (const float4*)w1;
        #pragma unroll 2
        for (int kt = 0; kt < 32; kt++) {
            float4 wv[4];
            #pragma unroll
            for (int m = 0; m < 4; m++) wv[m] = w1v4[(ni * 4 + m) * 32 + kt];
            ulonglong2 e2[4][2];
            #pragma unroll
            for (int kk = 0; kk < 4; kk++) {
                const ulonglong2* ep = (const ulonglong2*)(sE_u + (4 * kt + kk) * 16 + pi * 4);
                e2[kk][0] = ep[0]; e2[kk][1] = ep[1];
            }
            #pragma unroll
            for (int kk = 0; kk < 4; kk++) {
                #pragma unroll
                for (int m = 0; m < 4; m++) {
                    float wf = (kk == 0) ? wv[m].x : (kk == 1) ? wv[m].y : (kk == 2) ? wv[m].z : wv[m].w;
                    ull wd = dup2(wf);
                    fma2(acc[m][0], e2[kk][0].x, wd, acc[m][0]);
                    fma2(acc[m][1], e2[kk][0].y, wd, acc[m][1]);
                    fma2(acc[m][2], e2[kk][1].x, wd, acc[m][2]);
                    fma2(acc[m][3], e2[kk][1].y, wd, acc[m][3]);
                }
            }
        }
        #pragma unroll
        for (int m = 0; m < 4; m++) {
            int n = ni * 4 + m;
            float bb = b1[n];
            #pragma unroll
            for (int j = 0; j < 4; j++) {
                float l = fmaxf(lo2(acc[m][j]) + bb, 0.f);
                float hgh = fmaxf(hi2(acc[m][j]) + bb, 0.f);
                sH_u[n * 16 + pi * 4 + j] = pack2(l, hgh);
            }
        }
    }
    __syncthreads();

    {   // GEMM2 + residual: thread = 4c x 4px; per nt: 4 LDS.128 + 32 FMA2 (8:1)
        int cg = tid >> 3;         // 0..31 -> c = cg*4..+3
        int pg = tid & 7;          // 0..7  -> px = pg*4..+3 (2 ull)
        ull acc[4][2];
        #pragma unroll
        for (int m = 0; m < 4; m++) { acc[m][0] = 0ull; acc[m][1] = 0ull; }
        const float4* w2v4 = (const float4*)w2;
        #pragma unroll 2
        for (int nt = 0; nt < 64; nt++) {
            float4 wv[4];
            #pragma unroll
            for (int m = 0; m < 4; m++) wv[m] = w2v4[(cg * 4 + m) * 64 + nt];
            ulonglong2 h2[4];
            #pragma unroll
            for (int kk = 0; kk < 4; kk++)
                h2[kk] = *(const ulonglong2*)(sH_u + (4 * nt + kk) * 16 + pg * 2);
            #pragma unroll
            for (int kk = 0; kk < 4; kk++) {
                #pragma unroll
                for (int m = 0; m < 4; m++) {
                    float wf = (kk == 0) ? wv[m].x : (kk == 1) ? wv[m].y : (kk == 2) ? wv[m].z : wv[m].w;
                    ull wd = dup2(wf);
                    fma2(acc[m][0], h2[kk].x, wd, acc[m][0]);
                    fma2(acc[m][1], h2[kk].y, wd, acc[m][1]);
                }
            }
        }
        #pragma unroll
        for (int m = 0; m < 4; m++) {
            int c = cg * 4 + m;
            ull bbd = dup2(b2[c]);
            float* og = out + (b * CC + c) * PP + (pix0 - b * PP) + pg * 4;
            #pragma unroll
            for (int j = 0; j < 2; j++) {
                ull ev = sE_u[c * 16 + pg * 2 + j];
                ull r;
                add2(r, acc[m][j], ev);
                add2(r, r, bbd);
                *(ull*)(og + 2 * j) = r;
            }
        }
    }
}

extern "C" void kernel_launch(void* const* d_in, const int* in_sizes, int n_in,
                              void* d_out, int out_size) {
    const float* x     = (const float*)d_in[0];
    const float* gamma = (const float*)d_in[1];
    const float* beta  = (const float*)d_in[2];
    const float* w1    = (const float*)d_in[3];
    const float* b1    = (const float*)d_in[4];
    const float* w2    = (const float*)d_in[5];
    const float* b2    = (const float*)d_in[6];
    float* out = (float*)d_out;

    dim3 gT(NT, 4, BB);
    k_t<<<gT, 256>>>(x);
    k_pix<<<BPP / 8, 256>>>();
    k_main<<<BPP / 8, 256>>>(gamma, beta);
    k_ffn<<<BPP / 32, 256>>>(w1, b1, w2, b2, out);
}

// round 16
// speedup vs baseline: 1.5128x; 1.5128x over previous
#include <cuda_runtime.h>
#include <math.h>

#define BB 2
#define CC 128
#define HH 48
#define WW 48
#define PP (HH*WW)      // 2304
#define BPP (BB*PP)     // 4608
#define HD 24
#define WIN 13
#define KK2 169
#define NG 32
#define NT 72

typedef unsigned long long ull;

// ---------------- scratch (static device globals; no allocation) ----------------
__device__ float g_xt[BB*PP*CC];         // x transposed, pixel-major [b,p,c]
__device__ float g_xn[BB*PP*CC];         // normalized x, pixel-major [pix][c]
__device__ float g_m[BPP];
__device__ float g_df[BPP];
__device__ int   g_dmin[BB];
__device__ int   g_dmax[BB];
__device__ float g_gps[BB*NG*NT];
__device__ float g_gpq[BB*NG*NT];
__device__ float g_mu[BB*NG];
__device__ float g_rstd[BB*NG];
__device__ float g_enh[BB*PP*CC];

__device__ __forceinline__ void fma2(ull& d, ull a, ull b, ull c) {
    asm("fma.rn.f32x2 %0, %1, %2, %3;" : "=l"(d) : "l"(a), "l"(b), "l"(c));
}
__device__ __forceinline__ void add2(ull& d, ull a, ull b) {
    asm("add.rn.f32x2 %0, %1, %2;" : "=l"(d) : "l"(a), "l"(b));
}
__device__ __forceinline__ ull dup2(float v) {
    ull r; unsigned u = __float_as_uint(v);
    asm("mov.b64 %0, {%1, %1};" : "=l"(r) : "r"(u));
    return r;
}
__device__ __forceinline__ ull pack2(float a, float b) {
    ull r; asm("mov.b64 %0, {%1, %2};" : "=l"(r) : "r"(__float_as_uint(a)), "r"(__float_as_uint(b)));
    return r;
}
__device__ __forceinline__ float lo2(ull v) { return __uint_as_float((unsigned)(v & 0xffffffffull)); }
__device__ __forceinline__ float hi2(ull v) { return __uint_as_float((unsigned)(v >> 32)); }
__device__ __forceinline__ int refl(int v, int n) {
    return v < 0 ? -v : (v >= n ? 2 * n - 2 - v : v);
}
// jax bilinear 24->48 weights (edge-renormalized triangle)
__device__ __forceinline__ void upw(int o, int& i0, float& w0, int& i1, float& w1v) {
    if (o & 1) { i0 = (o - 1) >> 1; i1 = i0 + 1; w0 = 0.75f; w1v = 0.25f;
                 if (i1 >= HD) { i1 = i0; w0 = 1.0f; w1v = 0.0f; } }
    else       { i1 = o >> 1; i0 = i1 - 1; w1v = 0.75f; w0 = 0.25f;
                 if (i0 < 0) { i0 = i1; w0 = 0.0f; w1v = 1.0f; } }
}

// ---------------- k_t: NCHW -> pixel-major transpose + GN partial sums + init ----------------
__global__ void __launch_bounds__(256) k_t(const float* __restrict__ x) {
    __shared__ float tile[32][33];
    __shared__ float sS[8][4], sQ[8][4];
    int tx = threadIdx.x & 31, ty = threadIdx.x >> 5;
    int tb = blockIdx.x, cb = blockIdx.y, b = blockIdx.z;
    if (tb == 0 && cb == 0 && b == 0 && threadIdx.x < BB) {
        g_dmin[threadIdx.x] = 0x7f7fffff; g_dmax[threadIdx.x] = 0;
    }
    int c0 = cb * 32, p0 = tb * 32;
    #pragma unroll
    for (int k = 0; k < 4; k++) {
        int c = c0 + ty + 8 * k;
        float v = x[(b * CC + c) * PP + p0 + tx];
        tile[ty + 8 * k][tx] = v;
        float s = v, q = v * v;
        #pragma unroll
        for (int off = 16; off; off >>= 1) {
            s += __shfl_xor_sync(~0u, s, off);
            q += __shfl_xor_sync(~0u, q, off);
        }
        if (tx == 0) { sS[ty][k] = s; sQ[ty][k] = q; }
    }
    __syncthreads();
    #pragma unroll
    for (int k = 0; k < 4; k++) {
        int p = p0 + ty + 8 * k;
        g_xt[(b * PP + p) * CC + c0 + tx] = tile[tx][ty + 8 * k];
    }
    if (threadIdx.x < 8) {
        int k = threadIdx.x >> 1, m = threadIdx.x & 1;
        float s = sS[4*m][k] + sS[4*m+1][k] + sS[4*m+2][k] + sS[4*m+3][k];
        float q = sQ[4*m][k] + sQ[4*m+1][k] + sQ[4*m+2][k] + sQ[4*m+3][k];
        int g = 8 * cb + threadIdx.x;
        g_gps[(b * NG + g) * NT + tb] = s;
        g_gpq[(b * NG + g) * NT + tb] = q;
    }
}

// ---------------- k_pix: warp/pixel; inline 2x2-mean taps, df, norm, GN finalize ----------------
__global__ void __launch_bounds__(256) k_pix() {
    if (blockIdx.x < BB * NG) {                   // GN finalize (g_gps from k_t)
        __shared__ float fs[NT], fq[NT];
        int bg = blockIdx.x;
        if (threadIdx.x < NT) {
            fs[threadIdx.x] = g_gps[bg * NT + threadIdx.x];
            fq[threadIdx.x] = g_gpq[bg * NT + threadIdx.x];
        }
        __syncthreads();
        if (threadIdx.x == 0) {
            float s = 0.f, q = 0.f;
            for (int i = 0; i < NT; i++) { s += fs[i]; q += fq[i]; }
            const float invn = 1.0f / (4.0f * PP);
            float mu = s * invn;
            float var = q * invn - mu * mu;
            g_mu[bg] = mu;
            g_rstd[bg] = rsqrtf(var + 1e-5f);
        }
    }

    int warp = threadIdx.x >> 5, lane = threadIdx.x & 31;
    int pix = blockIdx.x * 8 + warp;              // 576*8 = 4608
    int b = pix / PP, p = pix - b * PP;
    int h = p / WW, w = p - h * WW;
    const float4 v4 = *(const float4*)(g_xt + pix * CC + 4 * lane);

    int r0, r1, c0, c1; float wr0, wr1, wc0, wc1;
    upw(h, r0, wr0, r1, wr1);
    upw(w, c0, wc0, c1, wc1);

    const float* xb = g_xt + b * PP * CC + 4 * lane;
    float4 dv[2][2];
    #pragma unroll
    for (int rr = 0; rr < 2; rr++) {
        int r = rr ? r1 : r0;
        #pragma unroll
        for (int cc2 = 0; cc2 < 2; cc2++) {
            int c = cc2 ? c1 : c0;
            const float* bp = xb + ((2 * r) * WW + 2 * c) * CC;
            float4 a0 = *(const float4*)(bp);
            float4 a1 = *(const float4*)(bp + CC);
            float4 a2 = *(const float4*)(bp + WW * CC);
            float4 a3 = *(const float4*)(bp + WW * CC + CC);
            dv[rr][cc2].x = 0.25f * (a0.x + a1.x + a2.x + a3.x);
            dv[rr][cc2].y = 0.25f * (a0.y + a1.y + a2.y + a3.y);
            dv[rr][cc2].z = 0.25f * (a0.z + a1.z + a2.z + a3.z);
            dv[rr][cc2].w = 0.25f * (a0.w + a1.w + a2.w + a3.w);
        }
    }
    float x0 = wr0 * (wc0 * dv[0][0].x + wc1 * dv[0][1].x) + wr1 * (wc0 * dv[1][0].x + wc1 * dv[1][1].x);
    float x1 = wr0 * (wc0 * dv[0][0].y + wc1 * dv[0][1].y) + wr1 * (wc0 * dv[1][0].y + wc1 * dv[1][1].y);
    float x2 = wr0 * (wc0 * dv[0][0].z + wc1 * dv[0][1].z) + wr1 * (wc0 * dv[1][0].z + wc1 * dv[1][1].z);
    float x3 = wr0 * (wc0 * dv[0][0].w + wc1 * dv[0][1].w) + wr1 * (wc0 * dv[1][0].w + wc1 * dv[1][1].w);

    float a = fabsf(v4.x - x0) + fabsf(v4.y - x1) + fabsf(v4.z - x2) + fabsf(v4.w - x3);
    float q = v4.x * v4.x + v4.y * v4.y + v4.z * v4.z + v4.w * v4.w;
    #pragma unroll
    for (int off = 16; off; off >>= 1) {
        a += __shfl_xor_sync(~0u, a, off);
        q += __shfl_xor_sync(~0u, q, off);
    }
    float m = fmaxf(sqrtf(q), 1e-12f);
    if (lane == 0) {
        g_df[pix] = a;
        atomicMin(&g_dmin[b], __float_as_int(a));
        atomicMax(&g_dmax[b], __float_as_int(a));
        g_m[pix] = m;
    }
    float inv = 1.0f / m;
    float4 o; o.x = v4.x * inv; o.y = v4.y * inv; o.z = v4.z * inv; o.w = v4.w * inv;
    *(float4*)(g_xn + pix * CC + 4 * lane) = o;
}

// ---------------- k_main: sims (multi-value butterfly, measured 34us) + stable top-k + gather + GN ----------------
__global__ void __launch_bounds__(256) k_main(const float* __restrict__ gamma,
                                              const float* __restrict__ beta) {
    int warp = threadIdx.x >> 5, lane = threadIdx.x & 31;
    int pix = blockIdx.x * 8 + warp;
    int b = pix / PP, p = pix - b * PP;
    int h = p / WW, w = p - h * WW;
    const float* xnb = g_xn + b * PP * CC;
    const float4 xp4 = *(const float4*)(xnb + p * CC + 4 * lane);

    float df = g_df[pix];
    float dmin = __int_as_float(g_dmin[b]);
    float dmax = __int_as_float(g_dmax[b]);
    float dn = (df - dmin) / (dmax - dmin + 1e-8f);
    int kcnt = (int)(1.0f + rintf(dn * 15.0f));
    if (kcnt < 1) kcnt = 1;
    if (kcnt > 16) kcnt = 16;

    int rbase[WIN], qo[WIN];
    #pragma unroll
    for (int t = 0; t < WIN; t++) {
        rbase[t] = refl(h + t - 6, HH) * WW * CC;
        qo[t]    = refl(w + t - 6, WW) * CC;
    }

    float sreg[6];
    #pragma unroll
    for (int r = 0; r < 6; r++) {
        float v[32];
        #pragma unroll
        for (int jj = 0; jj < 32; jj++) {
            const int kk = r * 32 + jj;
            const int ii = (kk < KK2) ? kk / WIN : 0;
            const int ij = (kk < KK2) ? kk - ii * WIN : 0;
            const float4 vq = *(const float4*)(xnb + rbase[ii] + qo[ij] + 4 * lane);
            v[jj] = xp4.x * vq.x + xp4.y * vq.y + xp4.z * vq.z + xp4.w * vq.w;
        }
        #pragma unroll
        for (int off = 16; off >= 1; off >>= 1) {
            bool up = (lane & off) != 0;
            #pragma unroll
            for (int j = 0; j < off; j++) {
                float send = up ? v[j] : v[j + off];
                float recv = __shfl_xor_sync(~0u, send, off);
                v[j] = (up ? v[j + off] : v[j]) + recv;
            }
        }
        sreg[r] = v[0];
    }
    if (160 + lane >= KK2) sreg[5] = -1e30f;

    unsigned taken = 0;
    int selk[16]; float selw[16];
    float sumexp = 0.f;
    #pragma unroll
    for (int it = 0; it < 16; it++) {
        if (it < kcnt) {
            float bv = -1e30f; int bt = 0;
            #pragma unroll
            for (int t = 0; t < 6; t++) {
                float cand = (taken & (1u << t)) ? -1e30f : sreg[t];
                if (cand > bv) { bv = cand; bt = t; }
            }
            int bk = lane + 32 * bt;
            #pragma unroll
            for (int off = 16; off; off >>= 1) {
                float ov = __shfl_xor_sync(~0u, bv, off);
                int   ok = __shfl_xor_sync(~0u, bk, off);
                if (ov > bv || (ov == bv && ok < bk)) { bv = ov; bk = ok; }
            }
            if (lane == (bk & 31)) taken |= (1u << (bk >> 5));
            float e = __expf(bv);
            selk[it] = bk; selw[it] = e; sumexp += e;
        }
    }

    float inv = 1.0f / sumexp;
    float4 out4 = make_float4(0.f, 0.f, 0.f, 0.f);
    #pragma unroll
    for (int it = 0; it < 16; it++) {
        if (it < kcnt) {
            int kk = selk[it];
            int ii = kk / WIN, jj = kk - ii * WIN;
            int r = refl(h + ii - 6, HH);
            int cq = refl(w + jj - 6, WW);
            int q = r * WW + cq;
            float wgt = selw[it] * inv * g_m[b * PP + q];
            const float4 vq = *(const float4*)(xnb + q * CC + 4 * lane);
            out4.x += wgt * vq.x; out4.y += wgt * vq.y;
            out4.z += wgt * vq.z; out4.w += wgt * vq.w;
        }
    }

    float mp = g_m[pix];
    float mu = g_mu[b * NG + lane];
    float rs = g_rstd[b * NG + lane];
    float4 gm  = *(const float4*)(gamma + 4 * lane);
    float4 bt4 = *(const float4*)(beta + 4 * lane);
    float4 e4;
    e4.x = out4.x + (xp4.x * mp - mu) * rs * gm.x + bt4.x;
    e4.y = out4.y + (xp4.y * mp - mu) * rs * gm.y + bt4.y;
    e4.z = out4.z + (xp4.z * mp - mu) * rs * gm.z + bt4.z;
    e4.w = out4.w + (xp4.w * mp - mu) * rs * gm.w + bt4.w;
    *(float4*)(g_enh + pix * CC + 4 * lane) = e4;
}

// ---------------- k_ffn: R10 tiling at 512 threads (16 warps/SM), f32x2, 48KB smem ----------------
__global__ void __launch_bounds__(512) k_ffn(const float* __restrict__ w1,
                                             const float* __restrict__ b1,
                                             const float* __restrict__ w2,
                                             const float* __restrict__ b2,
                                             float* __restrict__ out) {
    __shared__ __align__(16) ull sE_u[128 * 16];   // [k][px-pair], 16KB
    __shared__ __align__(16) ull sH_u[256 * 16];   // [n][px-pair], 32KB
    float* sE_f = (float*)sE_u;
    int tid = threadIdx.x;
    int pix0 = blockIdx.x * 32;
    int b = pix0 / PP;

    {   // stage E transposed (coalesced float4; 1024 loads over 512 threads)
        const float4* eg = (const float4*)(g_enh + pix0 * CC);
        #pragma unroll
        for (int i = 0; i < 2; i++) {
            int idx = tid + 512 * i;
            int p = idx >> 5, c4 = idx & 31;
            float4 v = eg[idx];
            sE_f[(4 * c4 + 0) * 32 + p] = v.x;
            sE_f[(4 * c4 + 1) * 32 + p] = v.y;
            sE_f[(4 * c4 + 2) * 32 + p] = v.z;
            sE_f[(4 * c4 + 3) * 32 + p] = v.w;
        }
    }
    __syncthreads();

    {   // GEMM1: thread = 4n x 4px; per kt: 4 LDG + 4 LDS.128 + 32 FMA2
        int pi = tid & 7;          // 8 px-groups x 4px (2 ull)
        int ni = tid >> 3;         // 0..63 -> n = ni*4..+3
        ull acc[4][2];
        #pragma unroll
        for (int m = 0; m < 4; m++) { acc[m][0] = 0ull; acc[m][1] = 0ull; }
        const float4* w1v4 = (const float4*)w1;
        #pragma unroll 2
        for (int kt = 0; kt < 32; kt++) {
            float4 wv[4];
            #pragma unroll
            for (int m = 0; m < 4; m++) wv[m] = w1v4[(ni * 4 + m) * 32 + kt];
            ulonglong2 e2[4];
            #pragma unroll
            for (int kk = 0; kk < 4; kk++)
                e2[kk] = *(const ulonglong2*)(sE_u + (4 * kt + kk) * 16 + pi * 2);
            #pragma unroll
            for (int kk = 0; kk < 4; kk++) {
                #pragma unroll
                for (int m = 0; m < 4; m++) {
                    float wf = (kk == 0) ? wv[m].x : (kk == 1) ? wv[m].y : (kk == 2) ? wv[m].z : wv[m].w;
                    ull wd = dup2(wf);
                    fma2(acc[m][0], e2[kk].x, wd, acc[m][0]);
                    fma2(acc[m][1], e2[kk].y, wd, acc[m][1]);
                }
            }
        }
        #pragma unroll
        for (int m = 0; m < 4; m++) {
            int n = ni * 4 + m;
            float bb = b1[n];
            #pragma unroll
            for (int j = 0; j < 2; j++) {
                float l = fmaxf(lo2(acc[m][j]) + bb, 0.f);
                float hgh = fmaxf(hi2(acc[m][j]) + bb, 0.f);
                sH_u[n * 16 + pi * 2 + j] = pack2(l, hgh);
            }
        }
    }
    __syncthreads();

    {   // GEMM2 + residual: thread = 2c x 4px; per nt: 2 LDG + 4 LDS.128 + 16 FMA2
        int ci = tid >> 3;         // 0..63 -> c = ci*2..+1
        int pg = tid & 7;          // 8 px-groups x 4px (2 ull)
        ull acc[2][2];
        acc[0][0] = acc[0][1] = acc[1][0] = acc[1][1] = 0ull;
        const float4* w2v4 = (const float4*)w2;
        #pragma unroll 2
        for (int nt = 0; nt < 64; nt++) {
            float4 wv[2];
            wv[0] = w2v4[(ci * 2 + 0) * 64 + nt];
            wv[1] = w2v4[(ci * 2 + 1) * 64 + nt];
            ulonglong2 h2[4];
            #pragma unroll
            for (int kk = 0; kk < 4; kk++)
                h2[kk] = *(const ulonglong2*)(sH_u + (4 * nt + kk) * 16 + pg * 2);
            #pragma unroll
            for (int kk = 0; kk < 4; kk++) {
                #pragma unroll
                for (int m = 0; m < 2; m++) {
                    float wf = (kk == 0) ? wv[m].x : (kk == 1) ? wv[m].y : (kk == 2) ? wv[m].z : wv[m].w;
                    ull wd = dup2(wf);
                    fma2(acc[m][0], h2[kk].x, wd, acc[m][0]);
                    fma2(acc[m][1], h2[kk].y, wd, acc[m][1]);
                }
            }
        }
        #pragma unroll
        for (int m = 0; m < 2; m++) {
            int c = ci * 2 + m;
            ull bbd = dup2(b2[c]);
            float* og = out + (b * CC + c) * PP + (pix0 - b * PP) + pg * 4;
            #pragma unroll
            for (int j = 0; j < 2; j++) {
                ull ev = sE_u[c * 16 + pg * 2 + j];
                ull r;
                add2(r, acc[m][j], ev);
                add2(r, r, bbd);
                *(ull*)(og + 2 * j) = r;
            }
        }
    }
}

extern "C" void kernel_launch(void* const* d_in, const int* in_sizes, int n_in,
                              void* d_out, int out_size) {
    const float* x     = (const float*)d_in[0];
    const float* gamma = (const float*)d_in[1];
    const float* beta  = (const float*)d_in[2];
    const float* w1    = (const float*)d_in[3];
    const float* b1    = (const float*)d_in[4];
    const float* w2    = (const float*)d_in[5];
    const float* b2    = (const float*)d_in[6];
    float* out = (float*)d_out;

    dim3 gT(NT, 4, BB);
    k_t<<<gT, 256>>>(x);
    k_pix<<<BPP / 8, 256>>>();
    k_main<<<BPP / 8, 256>>>(gamma, beta);
    k_ffn<<<BPP / 32, 512>>>(w1, b1, w2, b2, out);
}